// round 13
// baseline (speedup 1.0000x reference)
#include <cuda_runtime.h>
#include <math.h>

// ---------------- problem constants ----------------
#define BDIM   2
#define RDIM   4096
#define NC     48
#define NI     48
#define NRAYS  (BDIM*RDIM)        // 8192
#define NPTS   (NRAYS*NC)         // 393216 per pass
#define HP     256
#define CP     32
#define PLANE_ELEMS (HP*HP)       // 65536
#define DLT    (0.9f/47.f)

// ---------------- scratch (static device globals; no allocs) ----------------
// combined channel-last planes: (bp, yx, 64ch) ; ch 0..31 = tex, 32..63 = shp
__device__ float4 g_T[6 * PLANE_ELEMS * 16];   // 100.7 MB
__device__ float4 g_samp[NRAYS*96];            // rgb + sigma (coarse 0..47, fine 48..95)
__device__ float  g_finez[NRAYS*NI];
__device__ unsigned int g_minmax[2];           // [0]=min bits, [1]=max bits (positive floats)

// ---------------- f32x2 packed helpers (Blackwell FFMA2) ----------------
typedef unsigned long long u64;
__device__ __forceinline__ u64 ffma2(u64 a, u64 b, u64 c) {
    u64 d; asm("fma.rn.f32x2 %0, %1, %2, %3;" : "=l"(d) : "l"(a), "l"(b), "l"(c)); return d;
}
__device__ __forceinline__ u64 pack2(float lo, float hi) {
    u64 d; asm("mov.b64 %0, {%1, %2};" : "=l"(d) : "f"(lo), "f"(hi)); return d;
}
__device__ __forceinline__ float2 unpack2(u64 v) {
    float2 r; asm("mov.b64 {%0, %1}, %2;" : "=f"(r.x), "=f"(r.y) : "l"(v)); return r;
}

__device__ __forceinline__ float fast_softplus(float x) {
    return fmaxf(x, 0.f) + __logf(1.f + __expf(-fabsf(x)));
}
__device__ __forceinline__ float fast_sigmoid_rgb(float x) {
    return 1.002f / (1.f + __expf(-x)) - 0.001f;
}

// ---------------- 1) transpose + interleave planes to channel-last ----------------
__global__ void transpose_kernel(const float* __restrict__ tex,
                                 const float* __restrict__ shp) {
    __shared__ float tile[64][33];
    int bp  = blockIdx.y;                  // 0..5
    int yx0 = blockIdx.x * 32;
    int tx = threadIdx.x, ty = threadIdx.y;   // 32 x 8

    const float* st = tex + (size_t)bp * CP * PLANE_ELEMS;
    const float* ss = shp + (size_t)bp * CP * PLANE_ELEMS;
#pragma unroll
    for (int i = 0; i < 4; i++) {
        int c = i * 8 + ty;
        tile[c][tx]      = st[(size_t)c * PLANE_ELEMS + yx0 + tx];
        tile[32 + c][tx] = ss[(size_t)c * PLANE_ELEMS + yx0 + tx];
    }
    __syncthreads();
    float* d = (float*)(g_T + ((size_t)bp * PLANE_ELEMS + yx0) * 16);
#pragma unroll
    for (int i = 0; i < 8; i++) {
        int lin = i * 256 + ty * 32 + tx;     // row = lin/64 (yx), c = lin%64
        d[lin] = tile[lin & 63][lin >> 6];
    }
}

__global__ void init_kernel() {
    g_minmax[0] = 0x7f800000u;  // +inf
    g_minmax[1] = 0u;           // 0.0f
}

// ---------------- 2) point kernel: 4 threads per point ----------------
// Block = 256 threads = 64 points x 4 channel-chunks (16 ch each).
__global__ __launch_bounds__(256, 4)
void point_kernel(const float* __restrict__ origins, const float* __restrict__ dirs,
                  const float* __restrict__ W1, const float* __restrict__ b1,
                  const float* __restrict__ W2, const float* __restrict__ b2,
                  const float* __restrict__ noise, int fine) {
    // WW[(kk*4 + c4)*17 + jj] : ulonglong2 = (W1[4kk+0..1][j], W1[4kk+2..3][j]) packed pairs,
    // padded so the 4 c4-chunks of a warp hit disjoint bank windows.
    __shared__ __align__(16) ulonglong2 WW[16 * 4 * 17];     // 17408 B
    __shared__ __align__(16) ulonglong2 f_s[64 * 17];        // 17408 B (features per point, padded)
    __shared__ __align__(16) float W2ts[4 * 64];             // W2ts[c*64 + j] = W2[j*4 + c]
    __shared__ float b1s[64];
    __shared__ float b2s[4];

    int tid = threadIdx.x;
    {
        float* WWf = (float*)WW;
        for (int i = tid; i < 4096; i += 256) {
            int k = i >> 6, j = i & 63;
            int kk = k >> 2, q = k & 3, c4w = j >> 4, jjw = j & 15;
            WWf[((kk * 4 + c4w) * 17 + jjw) * 4 + q] = W1[i];
        }
        for (int i = tid; i < 256; i += 256) W2ts[(i & 3) * 64 + (i >> 2)] = W2[i];
        if (tid < 64) b1s[tid] = b1[tid];
        if (tid < 4)  b2s[tid] = b2[tid];
    }
    __syncthreads();

    int p   = tid >> 2;        // point within block
    int c4  = tid & 3;         // channel chunk
    int pid = blockIdx.x * 64 + p;
    int ray = pid / NC;
    int s   = pid - ray * NC;
    int b   = ray >> 12;       // RDIM = 4096

    float ox = origins[ray*3+0], oy = origins[ray*3+1], oz = origins[ray*3+2];
    float dx = dirs[ray*3+0],    dy = dirs[ray*3+1],    dz = dirs[ray*3+2];
    float inv = rsqrtf(dx*dx + dy*dy + dz*dz);
    dx *= inv; dy *= inv; dz *= inv;

    float z;
    if (fine) z = g_finez[pid];
    else      z = 0.1f + DLT * ((float)s + noise[pid]);
    float cx = ox + z*dx, cy = oy + z*dy, cz = oz + z*dz;

    // ---- phase 1: gather 16 channels over 3 planes x 4 taps ----
    u64 acc[8];
#pragma unroll
    for (int i = 0; i < 8; i++) acc[i] = 0ull;

    float gus[3] = {cx, cx, cz};
    float gvs[3] = {cy, cz, cx};
    const float* baseT = (const float*)g_T + (size_t)b * 3 * PLANE_ELEMS * 64 + c4 * 16;
#pragma unroll
    for (int p3 = 0; p3 < 3; p3++) {
        const float* P = baseT + (size_t)p3 * PLANE_ELEMS * 64;
        float px = (gus[p3] + 1.f) * 128.f - 0.5f;
        float py = (gvs[p3] + 1.f) * 128.f - 0.5f;
        float fx0 = floorf(px), fy0 = floorf(py);
        int x0 = (int)fx0, y0 = (int)fy0;
        float fx = px - fx0, fy = py - fy0;
#pragma unroll
        for (int dy2 = 0; dy2 < 2; dy2++) {
#pragma unroll
            for (int dx2 = 0; dx2 < 2; dx2++) {
                int xi = x0 + dx2, yi = y0 + dy2;
                float w = (dx2 ? fx : 1.f - fx) * (dy2 ? fy : 1.f - fy) * (1.f / 3.f);
                bool valid = (xi >= 0) & (xi < HP) & (yi >= 0) & (yi < HP);
                w = valid ? w : 0.f;
                int xc = min(max(xi, 0), HP - 1);
                int yc = min(max(yi, 0), HP - 1);
                const ulonglong2* q = (const ulonglong2*)(P + (size_t)(yc * HP + xc) * 64);
                u64 w2 = pack2(w, w);
#pragma unroll
                for (int i = 0; i < 4; i++) {
                    ulonglong2 v = q[i];
                    acc[2*i]   = ffma2(w2, v.x, acc[2*i]);
                    acc[2*i+1] = ffma2(w2, v.y, acc[2*i+1]);
                }
            }
        }
    }
#pragma unroll
    for (int i = 0; i < 4; i++)
        f_s[p * 17 + c4 * 4 + i] = make_ulonglong2(acc[2*i], acc[2*i+1]);
    __syncthreads();

    // ---- phase 2: this thread computes h[j] for j = c4*16 + (0..15), in two 8-blocks ----
    const ulonglong2* fsp = &f_s[p * 17];
    u64 oacc[4] = {0ull, 0ull, 0ull, 0ull};
#pragma unroll
    for (int h = 0; h < 2; h++) {
        u64 a1[8];
#pragma unroll
        for (int j = 0; j < 8; j++) a1[j] = 0ull;
#pragma unroll
        for (int kk = 0; kk < 16; kk++) {
            ulonglong2 fv = fsp[kk];
            const ulonglong2* wrow = &WW[(kk * 4 + c4) * 17 + h * 8];
#pragma unroll
            for (int j = 0; j < 8; j++) {
                ulonglong2 ww = wrow[j];
                a1[j] = ffma2(fv.x, ww.x, a1[j]);
                a1[j] = ffma2(fv.y, ww.y, a1[j]);
            }
        }
        float hh[8];
#pragma unroll
        for (int j = 0; j < 8; j++) {
            float2 pq = unpack2(a1[j]);
            hh[j] = fast_softplus(pq.x + pq.y + b1s[c4 * 16 + h * 8 + j]);
        }
#pragma unroll
        for (int t = 0; t < 4; t++) {
            u64 hp = pack2(hh[2*t], hh[2*t+1]);
#pragma unroll
            for (int c = 0; c < 4; c++) {
                u64 wv = ((const u64*)(W2ts + c * 64))[c4 * 8 + h * 4 + t];
                oacc[c] = ffma2(hp, wv, oacc[c]);
            }
        }
    }
    float o[4];
#pragma unroll
    for (int c = 0; c < 4; c++) { float2 e = unpack2(oacc[c]); o[c] = e.x + e.y; }
#pragma unroll
    for (int c = 0; c < 4; c++) o[c] += __shfl_xor_sync(0xffffffffu, o[c], 1);
#pragma unroll
    for (int c = 0; c < 4; c++) o[c] += __shfl_xor_sync(0xffffffffu, o[c], 2);

    if (c4 == 0) {
        float sg = o[0] + b2s[0];
        float rr = fast_sigmoid_rgb(o[1] + b2s[1]);
        float gg = fast_sigmoid_rgb(o[2] + b2s[2]);
        float bb = fast_sigmoid_rgb(o[3] + b2s[3]);
        g_samp[ray*96 + s + (fine ? 48 : 0)] = make_float4(rr, gg, bb, sg);
    }
}

// ---------------- 3) importance sampling (1 thread / ray) ----------------
__global__ void imp_kernel(const float* __restrict__ noise,
                           const float* __restrict__ impu) {
    int ray = blockIdx.x * blockDim.x + threadIdx.x;
    if (ray >= NRAYS) return;

    float z[48];
#pragma unroll
    for (int i = 0; i < 48; i++)
        z[i] = 0.1f + DLT * ((float)i + noise[ray*48 + i]);

    float w[47];
    float T = 1.f;
    float sp = g_samp[ray*96].w;
#pragma unroll
    for (int i = 0; i < 47; i++) {
        float sc = g_samp[ray*96 + i + 1].w;
        float dens  = fast_softplus(0.5f*(sp + sc) - 1.f);
        float alpha = 1.f - __expf(-dens * (z[i+1] - z[i]));
        w[i] = alpha * T;
        T *= (1.f - alpha + 1e-10f);
        sp = sc;
    }

    float bwv[45];
    float S = 0.f;
#pragma unroll
    for (int j = 1; j <= 45; j++) {
        float mj  = fmaxf(w[j-1], w[j]);
        float mj1 = fmaxf(w[j],   w[j+1]);
        float bw = 0.5f * (mj + mj1) + 0.01f;
        bwv[j-1] = bw; S += bw;
    }
    float invS = 1.f / S;
    float C[46];
    C[0] = 0.f;
#pragma unroll
    for (int j = 1; j <= 45; j++) C[j] = C[j-1] + bwv[j-1] * invS;

    atomicMin(&g_minmax[0], __float_as_uint(z[0]));
    atomicMax(&g_minmax[1], __float_as_uint(z[47]));

    for (int i = 0; i < 48; i++) {
        float u = impu[ray*48 + i];
        int ind = 0;
#pragma unroll
        for (int j = 0; j < 46; j++) ind += (C[j] <= u) ? 1 : 0;  // searchsorted right
        int below = ind - 1; if (below < 0) below = 0;
        int above = ind;     if (above > 45) above = 45;
        float c0 = C[below], c1 = C[above];
        float den = c1 - c0; if (den < 1e-5f) den = 1.f;
        float t = (u - c0) / den;
        float bb0 = 0.5f * (z[below] + z[below+1]);   // bins = z_mid
        float bb1 = 0.5f * (z[above] + z[above+1]);
        g_finez[ray*48 + i] = bb0 + t * (bb1 - bb0);
    }
}

// ---------------- 4) final: rank-sort + merge + march (1 thread / ray) ----------------
__global__ void final_kernel(const float* __restrict__ noise,
                             float* __restrict__ out) {
    int ray = blockIdx.x * blockDim.x + threadIdx.x;
    if (ray >= NRAYS) return;

    float zc[48];
#pragma unroll
    for (int i = 0; i < 48; i++)
        zc[i] = 0.1f + DLT * ((float)i + noise[ray*48 + i]);

    float fz[48];
#pragma unroll
    for (int i = 0; i < 48; i++) fz[i] = g_finez[ray*48 + i];

    // branchless stable rank sort of fine depths
    float sz[48]; int sid[48];
    for (int i = 0; i < 48; i++) {
        float v = fz[i];
        int r = 0;
#pragma unroll
        for (int j = 0; j < 48; j++)
            r += (fz[j] < v) || (fz[j] == v && j < i);
        sz[r] = v; sid[r] = i;
    }

    // two-pointer merge (coarse first on ties = stable argsort of concat) + march
    int ic = 0, iff = 0;
    float T = 1.f, accr = 0.f, accg = 0.f, accb = 0.f, wz = 0.f, ws = 0.f;
    float pz = 0.f; float4 ps = make_float4(0.f, 0.f, 0.f, 0.f);
    for (int step = 0; step < 96; step++) {
        float zcur; float4 scur;
        bool takec = (ic < 48) && (iff >= 48 || zc[ic] <= sz[iff]);
        if (takec) { zcur = zc[ic]; scur = g_samp[ray*96 + ic]; ic++; }
        else       { zcur = sz[iff]; scur = g_samp[ray*96 + 48 + sid[iff]]; iff++; }
        if (step > 0) {
            float dlt   = zcur - pz;
            float dens  = fast_softplus(0.5f*(ps.w + scur.w) - 1.f);
            float alpha = 1.f - __expf(-dens * dlt);
            float wgt   = alpha * T;
            accr += wgt * 0.5f * (ps.x + scur.x);
            accg += wgt * 0.5f * (ps.y + scur.y);
            accb += wgt * 0.5f * (ps.z + scur.z);
            wz   += wgt * 0.5f * (pz + zcur);
            ws   += wgt;
            T *= (1.f - alpha + 1e-10f);
        }
        pz = zcur; ps = scur;
    }

    float d = wz / ws;                 // nan/inf -> 0
    if (!isfinite(d)) d = 0.f;
    float gmin = __uint_as_float(g_minmax[0]);
    float gmax = __uint_as_float(g_minmax[1]);
    d = fminf(fmaxf(d, gmin), gmax);

    out[ray*3 + 0] = accr * 2.f - 1.f;
    out[ray*3 + 1] = accg * 2.f - 1.f;
    out[ray*3 + 2] = accb * 2.f - 1.f;
    out[NRAYS*3 + ray] = d;
    out[NRAYS*4 + ray] = ws;
}

// ---------------- launch ----------------
extern "C" void kernel_launch(void* const* d_in, const int* in_sizes, int n_in,
                              void* d_out, int out_size) {
    const float* tex   = (const float*)d_in[0];
    const float* shp   = (const float*)d_in[1];
    const float* orig  = (const float*)d_in[2];
    const float* dirs  = (const float*)d_in[3];
    const float* W1    = (const float*)d_in[4];
    const float* b1    = (const float*)d_in[5];
    const float* W2    = (const float*)d_in[6];
    const float* b2    = (const float*)d_in[7];
    const float* noise = (const float*)d_in[8];
    const float* impu  = (const float*)d_in[9];
    float* out = (float*)d_out;

    transpose_kernel<<<dim3(PLANE_ELEMS/32, 6), dim3(32, 8)>>>(tex, shp);
    init_kernel<<<1, 1>>>();
    point_kernel<<<NPTS/64, 256>>>(orig, dirs, W1, b1, W2, b2, noise, 0);
    imp_kernel<<<NRAYS/32, 32>>>(noise, impu);
    point_kernel<<<NPTS/64, 256>>>(orig, dirs, W1, b1, W2, b2, noise, 1);
    final_kernel<<<NRAYS/32, 32>>>(noise, out);
}

// round 14
// speedup vs baseline: 1.0111x; 1.0111x over previous
#include <cuda_runtime.h>
#include <math.h>

// ---------------- problem constants ----------------
#define BDIM   2
#define RDIM   4096
#define NC     48
#define NI     48
#define NRAYS  (BDIM*RDIM)        // 8192
#define NPTS   (NRAYS*NC)         // 393216 per pass
#define HP     256
#define CP     32
#define PLANE_ELEMS (HP*HP)       // 65536
#define DLT    (0.9f/47.f)

// ---------------- scratch (static device globals; no allocs) ----------------
// combined channel-last planes: (bp, yx, 64ch) ; ch 0..31 = tex, 32..63 = shp
__device__ float4 g_T[6 * PLANE_ELEMS * 16];   // 100.7 MB
__device__ float4 g_samp[NRAYS*96];            // rgb + sigma (coarse 0..47, fine 48..95)
__device__ float  g_finez[NRAYS*NI];
__device__ unsigned int g_minmax[2];           // [0]=min bits, [1]=max bits (positive floats)

// ---------------- f32x2 packed helpers (Blackwell FFMA2) ----------------
typedef unsigned long long u64;
__device__ __forceinline__ u64 ffma2(u64 a, u64 b, u64 c) {
    u64 d; asm("fma.rn.f32x2 %0, %1, %2, %3;" : "=l"(d) : "l"(a), "l"(b), "l"(c)); return d;
}
__device__ __forceinline__ u64 pack2(float lo, float hi) {
    u64 d; asm("mov.b64 %0, {%1, %2};" : "=l"(d) : "f"(lo), "f"(hi)); return d;
}
__device__ __forceinline__ float2 unpack2(u64 v) {
    float2 r; asm("mov.b64 {%0, %1}, %2;" : "=f"(r.x), "=f"(r.y) : "l"(v)); return r;
}

__device__ __forceinline__ float fast_softplus(float x) {
    return fmaxf(x, 0.f) + __logf(1.f + __expf(-fabsf(x)));
}
__device__ __forceinline__ float fast_sigmoid_rgb(float x) {
    return 1.002f / (1.f + __expf(-x)) - 0.001f;
}

// ---------------- 1) transpose + interleave planes to channel-last ----------------
__global__ void transpose_kernel(const float* __restrict__ tex,
                                 const float* __restrict__ shp) {
    __shared__ float tile[64][33];
    int bp  = blockIdx.y;                  // 0..5
    int yx0 = blockIdx.x * 32;
    int tx = threadIdx.x, ty = threadIdx.y;   // 32 x 8

    const float* st = tex + (size_t)bp * CP * PLANE_ELEMS;
    const float* ss = shp + (size_t)bp * CP * PLANE_ELEMS;
#pragma unroll
    for (int i = 0; i < 4; i++) {
        int c = i * 8 + ty;
        tile[c][tx]      = st[(size_t)c * PLANE_ELEMS + yx0 + tx];
        tile[32 + c][tx] = ss[(size_t)c * PLANE_ELEMS + yx0 + tx];
    }
    __syncthreads();
    float* d = (float*)(g_T + ((size_t)bp * PLANE_ELEMS + yx0) * 16);
#pragma unroll
    for (int i = 0; i < 8; i++) {
        int lin = i * 256 + ty * 32 + tx;     // row = lin/64 (yx), c = lin%64
        d[lin] = tile[lin & 63][lin >> 6];
    }
}

__global__ void init_kernel() {
    g_minmax[0] = 0x7f800000u;  // +inf
    g_minmax[1] = 0u;           // 0.0f
}

// ---------------- 2) point kernel: 4 threads per point ----------------
// Block = 256 threads = 64 points x 4 channel-chunks (16 ch each).
__global__ __launch_bounds__(256, 4)
void point_kernel(const float* __restrict__ origins, const float* __restrict__ dirs,
                  const float* __restrict__ W1, const float* __restrict__ b1,
                  const float* __restrict__ W2, const float* __restrict__ b2,
                  const float* __restrict__ noise, int fine) {
    // WW[(kk*4 + c4)*17 + jj] : ulonglong2 = (W1[4kk+0..1][j], W1[4kk+2..3][j]) packed pairs,
    // padded so the 4 c4-chunks of a warp hit disjoint bank windows.
    __shared__ __align__(16) ulonglong2 WW[16 * 4 * 17];     // 17408 B
    __shared__ __align__(16) ulonglong2 f_s[64 * 17];        // 17408 B (features per point, padded)
    __shared__ __align__(16) float W2ts[4 * 64];             // W2ts[c*64 + j] = W2[j*4 + c]
    __shared__ float b1s[64];
    __shared__ float b2s[4];

    int tid = threadIdx.x;
    {
        float* WWf = (float*)WW;
        for (int i = tid; i < 4096; i += 256) {
            int k = i >> 6, j = i & 63;
            int kk = k >> 2, q = k & 3, c4w = j >> 4, jjw = j & 15;
            WWf[((kk * 4 + c4w) * 17 + jjw) * 4 + q] = W1[i];
        }
        for (int i = tid; i < 256; i += 256) W2ts[(i & 3) * 64 + (i >> 2)] = W2[i];
        if (tid < 64) b1s[tid] = b1[tid];
        if (tid < 4)  b2s[tid] = b2[tid];
    }
    __syncthreads();

    int p   = tid >> 2;        // point within block
    int c4  = tid & 3;         // channel chunk
    int pid = blockIdx.x * 64 + p;
    int ray = pid / NC;
    int s   = pid - ray * NC;
    int b   = ray >> 12;       // RDIM = 4096

    float ox = origins[ray*3+0], oy = origins[ray*3+1], oz = origins[ray*3+2];
    float dx = dirs[ray*3+0],    dy = dirs[ray*3+1],    dz = dirs[ray*3+2];
    float inv = rsqrtf(dx*dx + dy*dy + dz*dz);
    dx *= inv; dy *= inv; dz *= inv;

    float z;
    if (fine) z = g_finez[pid];
    else      z = 0.1f + DLT * ((float)s + noise[pid]);
    float cx = ox + z*dx, cy = oy + z*dy, cz = oz + z*dz;

    // ---- phase 1: gather 16 channels over 3 planes x 4 taps ----
    u64 acc[8];
#pragma unroll
    for (int i = 0; i < 8; i++) acc[i] = 0ull;

    float gus[3] = {cx, cx, cz};
    float gvs[3] = {cy, cz, cx};
    const float* baseT = (const float*)g_T + (size_t)b * 3 * PLANE_ELEMS * 64 + c4 * 16;
#pragma unroll
    for (int p3 = 0; p3 < 3; p3++) {
        const float* P = baseT + (size_t)p3 * PLANE_ELEMS * 64;
        float px = (gus[p3] + 1.f) * 128.f - 0.5f;
        float py = (gvs[p3] + 1.f) * 128.f - 0.5f;
        float fx0 = floorf(px), fy0 = floorf(py);
        int x0 = (int)fx0, y0 = (int)fy0;
        float fx = px - fx0, fy = py - fy0;
#pragma unroll
        for (int dy2 = 0; dy2 < 2; dy2++) {
#pragma unroll
            for (int dx2 = 0; dx2 < 2; dx2++) {
                int xi = x0 + dx2, yi = y0 + dy2;
                float w = (dx2 ? fx : 1.f - fx) * (dy2 ? fy : 1.f - fy) * (1.f / 3.f);
                bool valid = (xi >= 0) & (xi < HP) & (yi >= 0) & (yi < HP);
                w = valid ? w : 0.f;
                int xc = min(max(xi, 0), HP - 1);
                int yc = min(max(yi, 0), HP - 1);
                const ulonglong2* q = (const ulonglong2*)(P + (size_t)(yc * HP + xc) * 64);
                u64 w2 = pack2(w, w);
#pragma unroll
                for (int i = 0; i < 4; i++) {
                    ulonglong2 v = q[i];
                    acc[2*i]   = ffma2(w2, v.x, acc[2*i]);
                    acc[2*i+1] = ffma2(w2, v.y, acc[2*i+1]);
                }
            }
        }
    }
#pragma unroll
    for (int i = 0; i < 4; i++)
        f_s[p * 17 + c4 * 4 + i] = make_ulonglong2(acc[2*i], acc[2*i+1]);
    __syncthreads();

    // ---- phase 2: this thread computes h[j] for j = c4*16 + (0..15), in two 8-blocks ----
    const ulonglong2* fsp = &f_s[p * 17];
    u64 oacc[4] = {0ull, 0ull, 0ull, 0ull};
#pragma unroll
    for (int h = 0; h < 2; h++) {
        u64 a1[8];
#pragma unroll
        for (int j = 0; j < 8; j++) a1[j] = 0ull;
#pragma unroll
        for (int kk = 0; kk < 16; kk++) {
            ulonglong2 fv = fsp[kk];
            const ulonglong2* wrow = &WW[(kk * 4 + c4) * 17 + h * 8];
#pragma unroll
            for (int j = 0; j < 8; j++) {
                ulonglong2 ww = wrow[j];
                a1[j] = ffma2(fv.x, ww.x, a1[j]);
                a1[j] = ffma2(fv.y, ww.y, a1[j]);
            }
        }
        float hh[8];
#pragma unroll
        for (int j = 0; j < 8; j++) {
            float2 pq = unpack2(a1[j]);
            hh[j] = fast_softplus(pq.x + pq.y + b1s[c4 * 16 + h * 8 + j]);
        }
#pragma unroll
        for (int t = 0; t < 4; t++) {
            u64 hp = pack2(hh[2*t], hh[2*t+1]);
#pragma unroll
            for (int c = 0; c < 4; c++) {
                u64 wv = ((const u64*)(W2ts + c * 64))[c4 * 8 + h * 4 + t];
                oacc[c] = ffma2(hp, wv, oacc[c]);
            }
        }
    }
    float o[4];
#pragma unroll
    for (int c = 0; c < 4; c++) { float2 e = unpack2(oacc[c]); o[c] = e.x + e.y; }
#pragma unroll
    for (int c = 0; c < 4; c++) o[c] += __shfl_xor_sync(0xffffffffu, o[c], 1);
#pragma unroll
    for (int c = 0; c < 4; c++) o[c] += __shfl_xor_sync(0xffffffffu, o[c], 2);

    if (c4 == 0) {
        float sg = o[0] + b2s[0];
        float rr = fast_sigmoid_rgb(o[1] + b2s[1]);
        float gg = fast_sigmoid_rgb(o[2] + b2s[2]);
        float bb = fast_sigmoid_rgb(o[3] + b2s[3]);
        g_samp[ray*96 + s + (fine ? 48 : 0)] = make_float4(rr, gg, bb, sg);
    }
}

// ---------------- 3) importance sampling (1 thread / ray) ----------------
__global__ void imp_kernel(const float* __restrict__ noise,
                           const float* __restrict__ impu) {
    int ray = blockIdx.x * blockDim.x + threadIdx.x;
    if (ray >= NRAYS) return;

    float z[48];
#pragma unroll
    for (int i = 0; i < 48; i++)
        z[i] = 0.1f + DLT * ((float)i + noise[ray*48 + i]);

    float w[47];
    float T = 1.f;
    float sp = g_samp[ray*96].w;
#pragma unroll
    for (int i = 0; i < 47; i++) {
        float sc = g_samp[ray*96 + i + 1].w;
        float dens  = fast_softplus(0.5f*(sp + sc) - 1.f);
        float alpha = 1.f - __expf(-dens * (z[i+1] - z[i]));
        w[i] = alpha * T;
        T *= (1.f - alpha + 1e-10f);
        sp = sc;
    }

    float bwv[45];
    float S = 0.f;
#pragma unroll
    for (int j = 1; j <= 45; j++) {
        float mj  = fmaxf(w[j-1], w[j]);
        float mj1 = fmaxf(w[j],   w[j+1]);
        float bw = 0.5f * (mj + mj1) + 0.01f;
        bwv[j-1] = bw; S += bw;
    }
    float invS = 1.f / S;
    float C[46];
    C[0] = 0.f;
#pragma unroll
    for (int j = 1; j <= 45; j++) C[j] = C[j-1] + bwv[j-1] * invS;

    atomicMin(&g_minmax[0], __float_as_uint(z[0]));
    atomicMax(&g_minmax[1], __float_as_uint(z[47]));

    for (int i = 0; i < 48; i++) {
        float u = impu[ray*48 + i];
        int ind = 0;
#pragma unroll
        for (int j = 0; j < 46; j++) ind += (C[j] <= u) ? 1 : 0;  // searchsorted right
        int below = ind - 1; if (below < 0) below = 0;
        int above = ind;     if (above > 45) above = 45;
        float c0 = C[below], c1 = C[above];
        float den = c1 - c0; if (den < 1e-5f) den = 1.f;
        float t = (u - c0) / den;
        float bb0 = 0.5f * (z[below] + z[below+1]);   // bins = z_mid
        float bb1 = 0.5f * (z[above] + z[above+1]);
        g_finez[ray*48 + i] = bb0 + t * (bb1 - bb0);
    }
}

// ---------------- 4) final: rank-sort + merge + march (1 thread / ray) ----------------
__global__ void final_kernel(const float* __restrict__ noise,
                             float* __restrict__ out) {
    int ray = blockIdx.x * blockDim.x + threadIdx.x;
    if (ray >= NRAYS) return;

    float zc[48];
#pragma unroll
    for (int i = 0; i < 48; i++)
        zc[i] = 0.1f + DLT * ((float)i + noise[ray*48 + i]);

    float fz[48];
#pragma unroll
    for (int i = 0; i < 48; i++) fz[i] = g_finez[ray*48 + i];

    // branchless stable rank sort of fine depths
    float sz[48]; int sid[48];
    for (int i = 0; i < 48; i++) {
        float v = fz[i];
        int r = 0;
#pragma unroll
        for (int j = 0; j < 48; j++)
            r += (fz[j] < v) || (fz[j] == v && j < i);
        sz[r] = v; sid[r] = i;
    }

    // two-pointer merge (coarse first on ties = stable argsort of concat) + march
    int ic = 0, iff = 0;
    float T = 1.f, accr = 0.f, accg = 0.f, accb = 0.f, wz = 0.f, ws = 0.f;
    float pz = 0.f; float4 ps = make_float4(0.f, 0.f, 0.f, 0.f);
    for (int step = 0; step < 96; step++) {
        float zcur; float4 scur;
        bool takec = (ic < 48) && (iff >= 48 || zc[ic] <= sz[iff]);
        if (takec) { zcur = zc[ic]; scur = g_samp[ray*96 + ic]; ic++; }
        else       { zcur = sz[iff]; scur = g_samp[ray*96 + 48 + sid[iff]]; iff++; }
        if (step > 0) {
            float dlt   = zcur - pz;
            float dens  = fast_softplus(0.5f*(ps.w + scur.w) - 1.f);
            float alpha = 1.f - __expf(-dens * dlt);
            float wgt   = alpha * T;
            accr += wgt * 0.5f * (ps.x + scur.x);
            accg += wgt * 0.5f * (ps.y + scur.y);
            accb += wgt * 0.5f * (ps.z + scur.z);
            wz   += wgt * 0.5f * (pz + zcur);
            ws   += wgt;
            T *= (1.f - alpha + 1e-10f);
        }
        pz = zcur; ps = scur;
    }

    float d = wz / ws;                 // nan/inf -> 0
    if (!isfinite(d)) d = 0.f;
    float gmin = __uint_as_float(g_minmax[0]);
    float gmax = __uint_as_float(g_minmax[1]);
    d = fminf(fmaxf(d, gmin), gmax);

    out[ray*3 + 0] = accr * 2.f - 1.f;
    out[ray*3 + 1] = accg * 2.f - 1.f;
    out[ray*3 + 2] = accb * 2.f - 1.f;
    out[NRAYS*3 + ray] = d;
    out[NRAYS*4 + ray] = ws;
}

// ---------------- launch ----------------
extern "C" void kernel_launch(void* const* d_in, const int* in_sizes, int n_in,
                              void* d_out, int out_size) {
    const float* tex   = (const float*)d_in[0];
    const float* shp   = (const float*)d_in[1];
    const float* orig  = (const float*)d_in[2];
    const float* dirs  = (const float*)d_in[3];
    const float* W1    = (const float*)d_in[4];
    const float* b1    = (const float*)d_in[5];
    const float* W2    = (const float*)d_in[6];
    const float* b2    = (const float*)d_in[7];
    const float* noise = (const float*)d_in[8];
    const float* impu  = (const float*)d_in[9];
    float* out = (float*)d_out;

    transpose_kernel<<<dim3(PLANE_ELEMS/32, 6), dim3(32, 8)>>>(tex, shp);
    init_kernel<<<1, 1>>>();
    point_kernel<<<NPTS/64, 256>>>(orig, dirs, W1, b1, W2, b2, noise, 0);
    imp_kernel<<<NRAYS/32, 32>>>(noise, impu);
    point_kernel<<<NPTS/64, 256>>>(orig, dirs, W1, b1, W2, b2, noise, 1);
    final_kernel<<<NRAYS/32, 32>>>(noise, out);
}